// round 2
// baseline (speedup 1.0000x reference)
#include <cuda_runtime.h>
#include <math.h>

// Problem constants
#define NN   20000      // nodes
#define EE   160000     // edges (without self loops)
#define ETOT 180000     // edges + self loops
#define BB   128        // graphs
#define NGG  10000

// ------------------------- scratch (device globals) -------------------------
__device__ float g_h   [NN * 128];      // current node features
__device__ float g_xw  [NN * 512];      // h @ W  -> (n, h, o)
__device__ float g_t   [NN * 256];      // h @ attA1
__device__ float g_hn  [NN * 128];      // pre-BN layer output
__device__ float g_es  [NN * 4];
__device__ float g_ed  [NN * 4];
__device__ float g_Wt  [128 * 512];     // W transposed to (f, h*128+o)
__device__ int   g_deg [NN];
__device__ int   g_off [NN + 1];
__device__ int   g_cur [NN];
__device__ int   g_csr [ETOT];
__device__ float g_bnsum[128];
__device__ float g_bnsq [128];
__device__ float g_lmu [128];
__device__ float g_linv[128];
__device__ float g_s   [NN];
__device__ int   g_gstart[BB];
__device__ int   g_gend  [BB];
__device__ float g_comb[BB * 192];
__device__ float g_z1p [BB * 256];
__device__ float g_z1  [BB * 256];
__device__ float g_z2p [BB * 128];
__device__ float g_z2  [BB * 128];
__device__ float g_nodebias[NGG];

// ------------------------------- setup kernels -------------------------------
__global__ void init_kernel() {
    int i = blockIdx.x * blockDim.x + threadIdx.x;
    if (i < NN) g_deg[i] = 0;
    if (i < BB) { g_gstart[i] = NN; g_gend[i] = 0; }
}

__global__ void copy_h_kernel(const float4* __restrict__ x) {
    int i = blockIdx.x * blockDim.x + threadIdx.x;
    if (i < NN * 32) ((float4*)g_h)[i] = x[i];
}

__global__ void nodebias_kernel(const float* __restrict__ Gemb) {
    int gid  = blockIdx.x * blockDim.x + threadIdx.x;
    int w    = gid >> 5;
    int lane = gid & 31;
    if (w >= NGG) return;
    float v = Gemb[w * 64 + lane] + Gemb[w * 64 + 32 + lane];
    #pragma unroll
    for (int o = 16; o; o >>= 1) v += __shfl_xor_sync(0xffffffffu, v, o);
    if (lane == 0) g_nodebias[w] = v * (1.0f / 64.0f);
}

__global__ void hist_kernel(const int* __restrict__ ei) {
    int e = blockIdx.x * blockDim.x + threadIdx.x;
    if (e >= ETOT) return;
    int dst = (e < EE) ? ei[EE + e] : (e - EE);
    atomicAdd(&g_deg[dst], 1);
}

__global__ void scan_kernel() {
    __shared__ int sh[1024];
    int t = threadIdx.x;
    int carry = 0;
    for (int base = 0; base < NN; base += 1024) {
        int v = (base + t < NN) ? g_deg[base + t] : 0;
        sh[t] = v;
        __syncthreads();
        for (int o = 1; o < 1024; o <<= 1) {
            int x = 0;
            if (t >= o) x = sh[t - o];
            __syncthreads();
            sh[t] += x;
            __syncthreads();
        }
        if (base + t < NN) {
            int excl = carry + sh[t] - v;
            g_off[base + t] = excl;
            g_cur[base + t] = excl;
        }
        carry += sh[1023];
        __syncthreads();
    }
    if (t == 0) g_off[NN] = carry;
}

__global__ void scatter_kernel(const int* __restrict__ ei) {
    int e = blockIdx.x * blockDim.x + threadIdx.x;
    if (e >= ETOT) return;
    int src, dst;
    if (e < EE) { src = ei[e]; dst = ei[EE + e]; }
    else        { src = e - EE; dst = e - EE; }
    int pos = atomicAdd(&g_cur[dst], 1);
    g_csr[pos] = src;
}

// ------------------------------- SGEMM (K=128) -------------------------------
// C[M x NC] = A[M x 128] * B[128 x NC], 128x128 block tile, 8x8 microtile.
template <int NC>
__device__ __forceinline__ void gemm_body(const float* __restrict__ A,
                                          const float* __restrict__ B,
                                          float* __restrict__ C, int M) {
    __shared__ float As[16][132];
    __shared__ float Bs[16][128];
    int tid = threadIdx.x;
    int tx = tid & 15, ty = tid >> 4;
    int row0 = blockIdx.y * 128;
    int col0 = blockIdx.x * 128;
    float acc[8][8];
    #pragma unroll
    for (int i = 0; i < 8; i++)
        #pragma unroll
        for (int j = 0; j < 8; j++) acc[i][j] = 0.0f;

    for (int k0 = 0; k0 < 128; k0 += 16) {
        #pragma unroll
        for (int hh = 0; hh < 2; hh++) {
            int m  = (tid >> 2) + hh * 64;
            int kq = (tid & 3) * 4;
            float4 v = make_float4(0.f, 0.f, 0.f, 0.f);
            if (row0 + m < M) v = *(const float4*)&A[(row0 + m) * 128 + k0 + kq];
            As[kq + 0][m] = v.x; As[kq + 1][m] = v.y;
            As[kq + 2][m] = v.z; As[kq + 3][m] = v.w;
        }
        #pragma unroll
        for (int hh = 0; hh < 2; hh++) {
            int k  = (tid >> 5) + hh * 8;
            int n4 = (tid & 31) * 4;
            *(float4*)&Bs[k][n4] = *(const float4*)&B[(k0 + k) * NC + col0 + n4];
        }
        __syncthreads();
        #pragma unroll
        for (int k = 0; k < 16; k++) {
            float4 a0 = *(const float4*)&As[k][ty * 8];
            float4 a1 = *(const float4*)&As[k][ty * 8 + 4];
            float4 b0 = *(const float4*)&Bs[k][tx * 8];
            float4 b1 = *(const float4*)&Bs[k][tx * 8 + 4];
            float a[8] = {a0.x, a0.y, a0.z, a0.w, a1.x, a1.y, a1.z, a1.w};
            float b[8] = {b0.x, b0.y, b0.z, b0.w, b1.x, b1.y, b1.z, b1.w};
            #pragma unroll
            for (int i = 0; i < 8; i++)
                #pragma unroll
                for (int j = 0; j < 8; j++) acc[i][j] += a[i] * b[j];
        }
        __syncthreads();
    }
    #pragma unroll
    for (int i = 0; i < 8; i++) {
        int r = row0 + ty * 8 + i;
        if (r < M) {
            float4 v0 = make_float4(acc[i][0], acc[i][1], acc[i][2], acc[i][3]);
            float4 v1 = make_float4(acc[i][4], acc[i][5], acc[i][6], acc[i][7]);
            *(float4*)&C[r * NC + col0 + tx * 8]     = v0;
            *(float4*)&C[r * NC + col0 + tx * 8 + 4] = v1;
        }
    }
}

__global__ __launch_bounds__(256) void gemm_xw_kernel() {
    gemm_body<512>(g_h, g_Wt, g_xw, NN);
}
__global__ __launch_bounds__(256) void gemm_att_kernel(const float* __restrict__ attA1) {
    gemm_body<256>(g_h, attA1, g_t, NN);
}

// ------------------------------- GAT per-layer -------------------------------
__global__ void transpose_w_kernel(const float* __restrict__ Wg, int l) {
    int idx = blockIdx.x * blockDim.x + threadIdx.x;
    if (idx >= 128 * 512) return;
    int f = idx >> 9;
    int r = idx & 511;
    int h = r >> 7;
    int o = r & 127;
    g_Wt[idx] = Wg[(((l * 4 + h) * 128) + f) * 128 + o];
}

__global__ void att_coef_kernel(const float* __restrict__ asrc,
                                const float* __restrict__ adst) {
    int gt = blockIdx.x * blockDim.x + threadIdx.x;
    if (gt < 128) { g_bnsum[gt] = 0.f; g_bnsq[gt] = 0.f; }
    int warpId = gt >> 5;
    int lane   = gt & 31;
    int nw = (gridDim.x * blockDim.x) >> 5;
    for (int t = warpId; t < NN * 4; t += nw) {
        int n = t >> 2, h = t & 3;
        const float* xp = &g_xw[n * 512 + h * 128];
        float s1 = 0.f, s2 = 0.f;
        #pragma unroll
        for (int j = 0; j < 4; j++) {
            float xv = xp[lane + 32 * j];
            s1 += xv * asrc[h * 128 + lane + 32 * j];
            s2 += xv * adst[h * 128 + lane + 32 * j];
        }
        #pragma unroll
        for (int o = 16; o; o >>= 1) {
            s1 += __shfl_xor_sync(0xffffffffu, s1, o);
            s2 += __shfl_xor_sync(0xffffffffu, s2, o);
        }
        if (lane == 0) { g_es[t] = s1; g_ed[t] = s2; }
    }
}

__device__ __forceinline__ float lrelu(float v) {
    return v > 0.f ? v : 0.2f * v;
}

__global__ void aggregate_kernel(const float* __restrict__ gbias) {
    int gt   = blockIdx.x * blockDim.x + threadIdx.x;
    int warp = gt >> 5;
    int lane = gt & 31;
    int nw = (gridDim.x * blockDim.x) >> 5;
    float csum[4] = {0.f, 0.f, 0.f, 0.f};
    float csq [4] = {0.f, 0.f, 0.f, 0.f};
    for (int n = warp; n < NN; n += nw) {
        int o0 = g_off[n], o1 = g_off[n + 1];
        float4 edn = *(const float4*)&g_ed[n * 4];

        // ---- pass 1: per-head max over edges (lanes split the edge list) ----
        float m0 = -1e30f, m1 = -1e30f, m2 = -1e30f, m3 = -1e30f;
        for (int e = o0 + lane; e < o1; e += 32) {
            int s = g_csr[e];
            float4 es = *(const float4*)&g_es[s * 4];
            m0 = fmaxf(m0, lrelu(es.x + edn.x));
            m1 = fmaxf(m1, lrelu(es.y + edn.y));
            m2 = fmaxf(m2, lrelu(es.z + edn.z));
            m3 = fmaxf(m3, lrelu(es.w + edn.w));
        }
        #pragma unroll
        for (int o = 16; o; o >>= 1) {
            m0 = fmaxf(m0, __shfl_xor_sync(0xffffffffu, m0, o));
            m1 = fmaxf(m1, __shfl_xor_sync(0xffffffffu, m1, o));
            m2 = fmaxf(m2, __shfl_xor_sync(0xffffffffu, m2, o));
            m3 = fmaxf(m3, __shfl_xor_sync(0xffffffffu, m3, o));
        }

        // ---- pass 2: single edge sweep, gather full xw row, weighted sum ----
        float den[4] = {0.f, 0.f, 0.f, 0.f};
        float acc[4][4];
        #pragma unroll
        for (int h = 0; h < 4; h++)
            #pragma unroll
            for (int j = 0; j < 4; j++) acc[h][j] = 0.f;

        for (int e = o0; e < o1; e++) {
            int s = g_csr[e];                       // broadcast load
            float4 es = *(const float4*)&g_es[s * 4];
            float w0 = __expf(lrelu(es.x + edn.x) - m0);
            float w1 = __expf(lrelu(es.y + edn.y) - m1);
            float w2 = __expf(lrelu(es.z + edn.z) - m2);
            float w3 = __expf(lrelu(es.w + edn.w) - m3);
            den[0] += w0; den[1] += w1; den[2] += w2; den[3] += w3;
            const float* xp = &g_xw[s * 512];
            float wv[4] = {w0, w1, w2, w3};
            #pragma unroll
            for (int h = 0; h < 4; h++) {
                #pragma unroll
                for (int j = 0; j < 4; j++)
                    acc[h][j] += wv[h] * xp[h * 128 + lane + 32 * j];
            }
        }

        #pragma unroll
        for (int j = 0; j < 4; j++) {
            float hsum = acc[0][j] / den[0] + acc[1][j] / den[1]
                       + acc[2][j] / den[2] + acc[3][j] / den[3];
            float v = hsum * 0.25f + gbias[lane + 32 * j];
            g_hn[n * 128 + lane + 32 * j] = v;
            csum[j] += v;
            csq[j]  += v * v;
        }
    }
    #pragma unroll
    for (int j = 0; j < 4; j++) {
        atomicAdd(&g_bnsum[lane + 32 * j], csum[j]);
        atomicAdd(&g_bnsq [lane + 32 * j], csq[j]);
    }
}

__global__ void bn_finalize_kernel() {
    int c = threadIdx.x;  // 128 threads
    float mu  = g_bnsum[c] * (1.0f / NN);
    float var = g_bnsq[c] * (1.0f / NN) - mu * mu;
    g_lmu[c]  = mu;
    g_linv[c] = rsqrtf(var + 1e-5f);
}

__global__ void bn_apply_kernel(const float* __restrict__ scale,
                                const float* __restrict__ bias, int addRes) {
    int idx = blockIdx.x * blockDim.x + threadIdx.x;   // NN*32 float4s
    if (idx >= NN * 32) return;
    int c4 = (idx & 31) * 4;
    float4 v = ((const float4*)g_hn)[idx];
    float4 r;
    r.x = fmaxf((v.x - g_lmu[c4+0]) * g_linv[c4+0] * scale[c4+0] + bias[c4+0], 0.f);
    r.y = fmaxf((v.y - g_lmu[c4+1]) * g_linv[c4+1] * scale[c4+1] + bias[c4+1], 0.f);
    r.z = fmaxf((v.z - g_lmu[c4+2]) * g_linv[c4+2] * scale[c4+2] + bias[c4+2], 0.f);
    r.w = fmaxf((v.w - g_lmu[c4+3]) * g_linv[c4+3] * scale[c4+3] + bias[c4+3], 0.f);
    if (addRes) {
        float4 h = ((const float4*)g_h)[idx];
        r.x += h.x; r.y += h.y; r.z += h.z; r.w += h.w;
    }
    ((float4*)g_h)[idx] = r;
}

// ------------------------------- pooling head -------------------------------
__global__ void score_kernel(const float* __restrict__ ab1,
                             const float* __restrict__ aA2,
                             const float* __restrict__ ab2) {
    int gt   = blockIdx.x * blockDim.x + threadIdx.x;
    int w    = gt >> 5;
    int lane = gt & 31;
    if (w >= NN) return;
    float acc = 0.f;
    #pragma unroll
    for (int j = lane; j < 256; j += 32)
        acc += tanhf(g_t[w * 256 + j] + ab1[j]) * aA2[j];
    #pragma unroll
    for (int o = 16; o; o >>= 1) acc += __shfl_xor_sync(0xffffffffu, acc, o);
    if (lane == 0) g_s[w] = acc + ab2[0];
}

__global__ void bounds_kernel(const int* __restrict__ batch) {
    int n = blockIdx.x * blockDim.x + threadIdx.x;
    if (n >= NN) return;
    int g = batch[n];
    atomicMin(&g_gstart[g], n);
    atomicMax(&g_gend[g], n + 1);
}

__global__ void pool_kernel(const int* __restrict__ brand0,
                            const int* __restrict__ brand1,
                            const float* __restrict__ Eb0,
                            const float* __restrict__ Eb1) {
    int g = blockIdx.x;     // BB blocks
    int t = threadIdx.x;    // 128 threads
    __shared__ float red[128];
    int st = g_gstart[g], en = g_gend[g];

    float m = -1e30f;
    for (int n = st + t; n < en; n += 128) m = fmaxf(m, g_s[n]);
    red[t] = m; __syncthreads();
    for (int o = 64; o; o >>= 1) { if (t < o) red[t] = fmaxf(red[t], red[t + o]); __syncthreads(); }
    m = red[0]; __syncthreads();

    float d = 0.f;
    for (int n = st + t; n < en; n += 128) d += __expf(g_s[n] - m);
    red[t] = d; __syncthreads();
    for (int o = 64; o; o >>= 1) { if (t < o) red[t] += red[t + o]; __syncthreads(); }
    d = red[0]; __syncthreads();

    float inv = (en > st) ? 1.0f / d : 0.0f;
    float acc = 0.f;
    for (int n = st; n < en; n++) {
        float w = __expf(g_s[n] - m) * inv;
        acc += w * g_h[n * 128 + t];
    }
    g_comb[g * 192 + t] = acc;
    if (t < 32)       g_comb[g * 192 + 128 + t]        = Eb0[brand0[g] * 32 + t];
    else if (t < 64)  g_comb[g * 192 + 160 + (t - 32)] = Eb1[brand1[g] * 32 + (t - 32)];
}

// --------------------------------- MLP head ---------------------------------
__global__ void mlp1_kernel(const float* __restrict__ P1w, const float* __restrict__ P1b) {
    int g = blockIdx.x;     // BB blocks
    int j = threadIdx.x;    // 256 threads
    __shared__ float cs[192];
    if (j < 192) cs[j] = g_comb[g * 192 + j];
    __syncthreads();
    float a = P1b[j];
    #pragma unroll 8
    for (int k = 0; k < 192; k++) a += cs[k] * P1w[k * 256 + j];
    g_z1p[g * 256 + j] = a;
}

__global__ void bnrelu1_kernel(const float* __restrict__ sc, const float* __restrict__ bi) {
    int j = blockIdx.x;     // 256 blocks (features)
    int t = threadIdx.x;    // 128 threads (rows)
    __shared__ float red[128];
    float x = g_z1p[t * 256 + j];
    red[t] = x; __syncthreads();
    for (int o = 64; o; o >>= 1) { if (t < o) red[t] += red[t + o]; __syncthreads(); }
    float mu = red[0] * (1.0f / 128.0f); __syncthreads();
    red[t] = x * x; __syncthreads();
    for (int o = 64; o; o >>= 1) { if (t < o) red[t] += red[t + o]; __syncthreads(); }
    float var = red[0] * (1.0f / 128.0f) - mu * mu;
    float v = (x - mu) * rsqrtf(var + 1e-5f) * sc[j] + bi[j];
    g_z1[t * 256 + j] = fmaxf(v, 0.0f);
}

__global__ void mlp2_kernel(const float* __restrict__ P2w, const float* __restrict__ P2b) {
    int g = blockIdx.x;     // BB blocks
    int j = threadIdx.x;    // 128 threads
    __shared__ float zs[256];
    zs[j]       = g_z1[g * 256 + j];
    zs[j + 128] = g_z1[g * 256 + j + 128];
    __syncthreads();
    float a = P2b[j];
    #pragma unroll 8
    for (int k = 0; k < 256; k++) a += zs[k] * P2w[k * 128 + j];
    g_z2p[g * 128 + j] = a;
}

__global__ void bnrelu2_kernel(const float* __restrict__ sc, const float* __restrict__ bi) {
    int j = blockIdx.x;     // 128 blocks
    int t = threadIdx.x;    // 128 threads
    __shared__ float red[128];
    float x = g_z2p[t * 128 + j];
    red[t] = x; __syncthreads();
    for (int o = 64; o; o >>= 1) { if (t < o) red[t] += red[t + o]; __syncthreads(); }
    float mu = red[0] * (1.0f / 128.0f); __syncthreads();
    red[t] = x * x; __syncthreads();
    for (int o = 64; o; o >>= 1) { if (t < o) red[t] += red[t + o]; __syncthreads(); }
    float var = red[0] * (1.0f / 128.0f) - mu * mu;
    float v = (x - mu) * rsqrtf(var + 1e-5f) * sc[j] + bi[j];
    g_z2[t * 128 + j] = fmaxf(v, 0.0f);
}

__global__ void final_kernel(const float* __restrict__ P3w,
                             const float* __restrict__ P3b,
                             float* __restrict__ out) {
    __shared__ float zs[16][128];
    int col = blockIdx.x * 256 + threadIdx.x;
    int r0  = blockIdx.y * 16;
    for (int i = threadIdx.x; i < 16 * 128; i += 256) {
        int r = i >> 7, k = i & 127;
        zs[r][k] = g_z2[(r0 + r) * 128 + k];
    }
    __syncthreads();
    if (col >= NGG) return;
    float acc[16];
    #pragma unroll
    for (int r = 0; r < 16; r++) acc[r] = 0.f;
    for (int k = 0; k < 128; k++) {
        float b = P3w[k * NGG + col];
        #pragma unroll
        for (int r = 0; r < 16; r++) acc[r] += zs[r][k] * b;
    }
    float add = P3b[col] + 0.1f * g_nodebias[col];
    #pragma unroll
    for (int r = 0; r < 16; r++) out[(r0 + r) * NGG + col] = acc[r] + add;
}

// ------------------------------- kernel_launch -------------------------------
extern "C" void kernel_launch(void* const* d_in, const int* in_sizes, int n_in,
                              void* d_out, int out_size) {
    const float* x        = (const float*)d_in[0];
    const int*   ei       = (const int*)  d_in[1];
    const int*   batch    = (const int*)  d_in[2];
    const int*   brand0   = (const int*)  d_in[3];
    const int*   brand1   = (const int*)  d_in[4];
    const float* Wg       = (const float*)d_in[5];
    const float* att_src  = (const float*)d_in[6];
    const float* att_dst  = (const float*)d_in[7];
    const float* gat_bias = (const float*)d_in[8];
    const float* bn_scale = (const float*)d_in[9];
    const float* bn_bias  = (const float*)d_in[10];
    const float* attA1    = (const float*)d_in[11];
    const float* attb1    = (const float*)d_in[12];
    const float* attA2    = (const float*)d_in[13];
    const float* attb2    = (const float*)d_in[14];
    const float* Eb0      = (const float*)d_in[15];
    const float* Eb1      = (const float*)d_in[16];
    const float* P1w      = (const float*)d_in[17];
    const float* P1b      = (const float*)d_in[18];
    const float* pbn1_s   = (const float*)d_in[19];
    const float* pbn1_b   = (const float*)d_in[20];
    const float* P2w      = (const float*)d_in[21];
    const float* P2b      = (const float*)d_in[22];
    const float* pbn2_s   = (const float*)d_in[23];
    const float* pbn2_b   = (const float*)d_in[24];
    const float* P3w      = (const float*)d_in[25];
    const float* P3b      = (const float*)d_in[26];
    const float* Gemb     = (const float*)d_in[27];
    float* out = (float*)d_out;

    // setup
    init_kernel<<<(NN + 255) / 256, 256>>>();
    copy_h_kernel<<<(NN * 32 + 255) / 256, 256>>>((const float4*)x);
    nodebias_kernel<<<(NGG * 32 + 255) / 256, 256>>>(Gemb);
    hist_kernel<<<(ETOT + 255) / 256, 256>>>(ei);
    scan_kernel<<<1, 1024>>>();
    scatter_kernel<<<(ETOT + 255) / 256, 256>>>(ei);

    // GAT layers
    for (int l = 0; l < 3; l++) {
        transpose_w_kernel<<<(128 * 512 + 255) / 256, 256>>>(Wg, l);
        gemm_xw_kernel<<<dim3(4, (NN + 127) / 128), 256>>>();
        att_coef_kernel<<<256, 256>>>(att_src + l * 512, att_dst + l * 512);
        aggregate_kernel<<<256, 256>>>(gat_bias + l * 128);
        bn_finalize_kernel<<<1, 128>>>();
        bn_apply_kernel<<<(NN * 32 + 255) / 256, 256>>>(bn_scale + l * 128,
                                                        bn_bias + l * 128,
                                                        l > 0 ? 1 : 0);
    }

    // attention pooling
    gemm_att_kernel<<<dim3(2, (NN + 127) / 128), 256>>>(attA1);
    score_kernel<<<(NN * 32 + 255) / 256, 256>>>(attb1, attA2, attb2);
    bounds_kernel<<<(NN + 255) / 256, 256>>>(batch);
    pool_kernel<<<BB, 128>>>(brand0, brand1, Eb0, Eb1);

    // MLP head
    mlp1_kernel<<<BB, 256>>>(P1w, P1b);
    bnrelu1_kernel<<<256, 128>>>(pbn1_s, pbn1_b);
    mlp2_kernel<<<BB, 128>>>(P2w, P2b);
    bnrelu2_kernel<<<128, 128>>>(pbn2_s, pbn2_b);
    final_kernel<<<dim3((NGG + 255) / 256, 8), 256>>>(P3w, P3b, out);
}